// round 14
// baseline (speedup 1.0000x reference)
#include <cuda_runtime.h>
#include <cuda_fp16.h>

#define NNODES 100000
#define FEAT   128
#define HEADS  8
#define HC     64          // HEADS*CH
#define E0     1600000     // edges in edge_index (self loops handled analytically)
#define NB     391         // ceil(NNODES/256) scan blocks
#define PACKW  40          // 32-bit words per node: 32 (64 fp16 h) + 8 (fp32 a_src)
#define BM     64          // gemm rows per block

// ---------------- scratch (device globals) ---------------------------------
__device__ unsigned int g_pack[NNODES * PACKW]; // 16 MB: fp16 h + fp32 a_src
__device__ float g_adst[NNODES * HEADS];        // 3.2 MB
__device__ float g_u[FEAT * 16];                // u = W @ [att_src | att_dst]
__device__ int   g_cnt[NNODES];                 // in-degree histogram
__device__ int   g_rowptr[NNODES + 1];          // CSR row pointers
__device__ int   g_fill[NNODES];                // scatter cursors
__device__ int   g_bsums[NB];                   // scan block sums
__device__ int   g_csr_src[E0];                 // CSR: src node per edge
__device__ int   g_is64;

// ---------------- tf32 mma helpers -----------------------------------------
__device__ __forceinline__ unsigned int f2tf32(float f) {
    unsigned int r;
    asm("cvt.rna.tf32.f32 %0, %1;" : "=r"(r) : "f"(f));
    return r;
}
__device__ __forceinline__ void mma_tf32(float c[4],
        unsigned int a0, unsigned int a1, unsigned int a2, unsigned int a3,
        unsigned int b0, unsigned int b1) {
    asm volatile(
        "mma.sync.aligned.m16n8k8.row.col.f32.tf32.tf32.f32 "
        "{%0,%1,%2,%3}, {%4,%5,%6,%7}, {%8,%9}, {%0,%1,%2,%3};"
        : "+f"(c[0]), "+f"(c[1]), "+f"(c[2]), "+f"(c[3])
        : "r"(a0), "r"(a1), "r"(a2), "r"(a3), "r"(b0), "r"(b1));
}

// ---------------- K0: zero histogram + detect dtype ------------------------
// int64 values in [0, N) have every odd 32-bit word == 0 (little endian).
__global__ void init_kernel(const int* __restrict__ ei32) {
    int t = blockIdx.x * blockDim.x + threadIdx.x;
    if (t < NNODES) g_cnt[t] = 0;
    if (t == 0) {
        int all_zero = 1;
#pragma unroll
        for (int i = 1; i < 16; i += 2) all_zero &= (ei32[i] == 0);
        g_is64 = all_zero;
    }
}

// ---------------- K0b: u = W @ [att_src | att_dst]  (exact fp32) -----------
__global__ void u_kernel(const float* __restrict__ W,
                         const float* __restrict__ att_src,
                         const float* __restrict__ att_dst) {
    int t = blockIdx.x * blockDim.x + threadIdx.x;
    if (t >= FEAT * 16) return;
    int k = t >> 4, j = t & 15;
    int head = j & 7;
    const float* att = (j < 8) ? (att_src + head * 8) : (att_dst + head * 8);
    float s = 0.f;
#pragma unroll
    for (int c = 0; c < 8; c++) s += W[k * HC + head * 8 + c] * att[c];
    g_u[t] = s;
}

// ---------------- K1: in-degree histogram (real edges only) ----------------
__global__ void hist_kernel(const void* __restrict__ ei) {
    int e = blockIdx.x * blockDim.x + threadIdx.x;
    if (e >= E0) return;
    int d = g_is64 ? ((const int*)ei)[2 * (E0 + e)]      // low word of int64
                   : ((const int*)ei)[E0 + e];
    atomicAdd(&g_cnt[d], 1);
}

// ---------------- K2a/b/c: exclusive prefix scan of g_cnt (shuffle) --------
__global__ void scanA_kernel() {
    int t = threadIdx.x, i = blockIdx.x * 256 + t;
    int lane = t & 31, w = t >> 5;
    int v = (i < NNODES) ? g_cnt[i] : 0;
    int x = v;
#pragma unroll
    for (int off = 1; off < 32; off <<= 1) {
        int y = __shfl_up_sync(0xFFFFFFFFu, x, off);
        if (lane >= off) x += y;
    }
    __shared__ int wsum[8];
    if (lane == 31) wsum[w] = x;
    __syncthreads();
    if (w == 0 && lane < 8) {
        int y = wsum[lane];
#pragma unroll
        for (int off = 1; off < 8; off <<= 1) {
            int z = __shfl_up_sync(0xFFu, y, off);
            if (lane >= off) y += z;
        }
        wsum[lane] = y;
    }
    __syncthreads();
    int incl = x + (w > 0 ? wsum[w - 1] : 0);
    if (i < NNODES) g_rowptr[i] = incl - v;       // block-local exclusive
    if (t == 255) g_bsums[blockIdx.x] = incl;
}

__global__ void scanB_kernel() {                  // 512 threads, 391 elems
    int t = threadIdx.x, lane = t & 31, w = t >> 5;
    int v = (t < NB) ? g_bsums[t] : 0;
    int x = v;
#pragma unroll
    for (int off = 1; off < 32; off <<= 1) {
        int y = __shfl_up_sync(0xFFFFFFFFu, x, off);
        if (lane >= off) x += y;
    }
    __shared__ int wsum[16];
    if (lane == 31) wsum[w] = x;
    __syncthreads();
    if (w == 0 && lane < 16) {
        int y = wsum[lane];
#pragma unroll
        for (int off = 1; off < 16; off <<= 1) {
            int z = __shfl_up_sync(0xFFFFu, y, off);
            if (lane >= off) y += z;
        }
        wsum[lane] = y;
    }
    __syncthreads();
    int incl = x + (w > 0 ? wsum[w - 1] : 0);
    if (t < NB) g_bsums[t] = incl - v;            // exclusive
}

__global__ void scanC_kernel() {
    int i = blockIdx.x * blockDim.x + threadIdx.x;
    if (i > NNODES) return;
    if (i == NNODES) { g_rowptr[NNODES] = E0; return; }
    int r = g_rowptr[i] + g_bsums[i >> 8];
    g_rowptr[i] = r;
    g_fill[i] = r;
}

// ---------------- K3: scatter edges into CSR -------------------------------
__global__ void scatter_kernel(const void* __restrict__ ei) {
    int e = blockIdx.x * blockDim.x + threadIdx.x;
    if (e >= E0) return;
    int s, d;
    const int* p = (const int*)ei;
    if (g_is64) { s = p[2 * e]; d = p[2 * (E0 + e)]; }
    else        { s = p[e];     d = p[E0 + e]; }
    int pos = atomicAdd(&g_fill[d], 1);
    g_csr_src[pos] = s;
}

// ---------------- K4: tf32 tensor-core h + exact fp32 logits ---------------
// 128 threads = 4 warps; warp w owns rows w*16..w*16+15 of a 64-row tile.
// h (messages, linear) via mma.sync tf32 (→ fp16 store, err class ~3e-4).
// Logits via exact fp32 dot x·u from the SAME smem tile (precision preserved
// where it enters the exp).
__global__ void __launch_bounds__(128) gemm_kernel(const float* __restrict__ x,
                                                   const float* __restrict__ W) {
    __shared__ __align__(16) float xs[BM][132];    // row-major, padded
    int tid = threadIdx.x;
    int warp = tid >> 5, lane = tid & 31;
    int rowBase = blockIdx.x * BM;

    // load x tile: 64 rows x 128 floats = 2048 float4, 16 per thread.
    // Each warp's 32 lanes cover exactly one row (conflict-free STS).
#pragma unroll
    for (int i = 0; i < 16; i++) {
        int idx = tid + i * 128;
        int r = idx >> 5, q = idx & 31;
        int grow = rowBase + r;
        float4 v = make_float4(0.f, 0.f, 0.f, 0.f);
        if (grow < NNODES)
            v = *(const float4*)(x + (size_t)grow * FEAT + q * 4);
        *(float4*)&xs[r][q * 4] = v;
    }
    __syncthreads();

    // ---- tensor-core part: D[16x64] per warp, K=128 in 16 chunks of 8 ----
    int g = lane >> 2, tg = lane & 3;              // groupID, threadInGroup
    float c[8][4];
#pragma unroll
    for (int n = 0; n < 8; n++)
#pragma unroll
        for (int j = 0; j < 4; j++) c[n][j] = 0.f;

    for (int kc = 0; kc < 16; kc++) {
        int k0 = kc * 8;
        unsigned int A0 = f2tf32(xs[warp * 16 + g]    [k0 + tg]);
        unsigned int A1 = f2tf32(xs[warp * 16 + g + 8][k0 + tg]);
        unsigned int A2 = f2tf32(xs[warp * 16 + g]    [k0 + tg + 4]);
        unsigned int A3 = f2tf32(xs[warp * 16 + g + 8][k0 + tg + 4]);
#pragma unroll
        for (int n = 0; n < 8; n++) {
            unsigned int B0 = f2tf32(__ldg(&W[(k0 + tg)     * HC + n * 8 + g]));
            unsigned int B1 = f2tf32(__ldg(&W[(k0 + tg + 4) * HC + n * 8 + g]));
            mma_tf32(c[n], A0, A1, A2, A3, B0, B1);
        }
    }

    // store h as fp16: c0/c1 are adjacent cols (2*tg, 2*tg+1) of row g;
    // c2/c3 same cols of row g+8 → one 32-bit half2 word each.
#pragma unroll
    for (int n = 0; n < 8; n++) {
        int rlo = rowBase + warp * 16 + g;
        int rhi = rlo + 8;
        __half2 lo = __floats2half2_rn(c[n][0], c[n][1]);
        __half2 hi = __floats2half2_rn(c[n][2], c[n][3]);
        if (rlo < NNODES) g_pack[(size_t)rlo * PACKW + n * 4 + tg] = *(unsigned int*)&lo;
        if (rhi < NNODES) g_pack[(size_t)rhi * PACKW + n * 4 + tg] = *(unsigned int*)&hi;
    }

    // ---- exact fp32 logits: lane = 2*r + half; 8 u-cols per lane ----------
    int r = lane >> 1, half = lane & 1;
    int srow = warp * 16 + r;
    int grow = rowBase + srow;
    float acc[8];
#pragma unroll
    for (int j = 0; j < 8; j++) acc[j] = 0.f;
    for (int k4 = 0; k4 < FEAT; k4 += 4) {
        float4 xv = *(const float4*)&xs[srow][k4];
        float xk[4] = {xv.x, xv.y, xv.z, xv.w};
#pragma unroll
        for (int kk = 0; kk < 4; kk++) {
            int k = k4 + kk;
            float4 ua = __ldg((const float4*)(g_u + k * 16 + half * 8));
            float4 ub = __ldg((const float4*)(g_u + k * 16 + half * 8 + 4));
            acc[0] += xk[kk] * ua.x; acc[1] += xk[kk] * ua.y;
            acc[2] += xk[kk] * ua.z; acc[3] += xk[kk] * ua.w;
            acc[4] += xk[kk] * ub.x; acc[5] += xk[kk] * ub.y;
            acc[6] += xk[kk] * ub.z; acc[7] += xk[kk] * ub.w;
        }
    }
    if (grow < NNODES) {
        if (half == 0) {        // a_src → packed row words 32..39
            float* dst = (float*)(g_pack + (size_t)grow * PACKW + 32);
            *(float4*)dst       = make_float4(acc[0], acc[1], acc[2], acc[3]);
            *(float4*)(dst + 4) = make_float4(acc[4], acc[5], acc[6], acc[7]);
        } else {                // a_dst
            float* dst = g_adst + (size_t)grow * 8;
            *(float4*)dst       = make_float4(acc[0], acc[1], acc[2], acc[3]);
            *(float4*)(dst + 4) = make_float4(acc[4], acc[5], acc[6], acc[7]);
        }
    }
}

// ---------------- K5: fused single-pass softmax + aggregate + bias + relu --
// One warp per destination node. Lane l owns channels {2l,2l+1}, head l>>2.
// Per edge: ONE 160B row (4 sectors fp16 h + 1 sector fp32 a_src).
__global__ void node_kernel(float* __restrict__ out, const float* __restrict__ bias) {
    int gw = (blockIdx.x * blockDim.x + threadIdx.x) >> 5;
    if (gw >= NNODES) return;
    int lane = threadIdx.x & 31;
    int beg = g_rowptr[gw], end = g_rowptr[gw + 1];
    int hd = lane >> 2;
    float adst = g_adst[gw * 8 + hd];

    // self loop
    const unsigned int* prow = g_pack + (size_t)gw * PACKW;
    float vs = __uint_as_float(prow[32 + hd]) + adst;
    vs = vs > 0.f ? vs : 0.2f * vs;
    float exs = __expf(vs);
    float2 hs = __half22float2(*(const __half2*)(prow + lane));
    float denom = exs;
    float ax = exs * hs.x, ay = exs * hs.y;

    int j = beg;
    for (; j + 4 <= end; j += 4) {
        int s0 = __ldg(&g_csr_src[j]);
        int s1 = __ldg(&g_csr_src[j + 1]);
        int s2 = __ldg(&g_csr_src[j + 2]);
        int s3 = __ldg(&g_csr_src[j + 3]);
        const unsigned int* p0 = g_pack + (size_t)s0 * PACKW;
        const unsigned int* p1 = g_pack + (size_t)s1 * PACKW;
        const unsigned int* p2 = g_pack + (size_t)s2 * PACKW;
        const unsigned int* p3 = g_pack + (size_t)s3 * PACKW;
        float e0 = __uint_as_float(p0[32 + hd]);
        float e1 = __uint_as_float(p1[32 + hd]);
        float e2 = __uint_as_float(p2[32 + hd]);
        float e3 = __uint_as_float(p3[32 + hd]);
        __half2 q0 = *(const __half2*)(p0 + lane);
        __half2 q1 = *(const __half2*)(p1 + lane);
        __half2 q2 = *(const __half2*)(p2 + lane);
        __half2 q3 = *(const __half2*)(p3 + lane);
        float v0 = e0 + adst; v0 = v0 > 0.f ? v0 : 0.2f * v0;
        float v1 = e1 + adst; v1 = v1 > 0.f ? v1 : 0.2f * v1;
        float v2 = e2 + adst; v2 = v2 > 0.f ? v2 : 0.2f * v2;
        float v3 = e3 + adst; v3 = v3 > 0.f ? v3 : 0.2f * v3;
        float x0 = __expf(v0), x1 = __expf(v1), x2 = __expf(v2), x3 = __expf(v3);
        float2 h0 = __half22float2(q0);
        float2 h1 = __half22float2(q1);
        float2 h2v = __half22float2(q2);
        float2 h3 = __half22float2(q3);
        denom += (x0 + x1) + (x2 + x3);
        ax += x0 * h0.x + x1 * h1.x + x2 * h2v.x + x3 * h3.x;
        ay += x0 * h0.y + x1 * h1.y + x2 * h2v.y + x3 * h3.y;
    }
    for (; j < end; j++) {
        int s = __ldg(&g_csr_src[j]);
        const unsigned int* p = g_pack + (size_t)s * PACKW;
        float v = __uint_as_float(p[32 + hd]) + adst;
        v = v > 0.f ? v : 0.2f * v;
        float ex = __expf(v);
        float2 hv = __half22float2(*(const __half2*)(p + lane));
        denom += ex;
        ax += ex * hv.x;
        ay += ex * hv.y;
    }

    float inv = __fdividef(1.f, denom + 1e-16f);
    float2 b = ((const float2*)bias)[lane];
    float ox = ax * inv + b.x, oy = ay * inv + b.y;
    ((float2*)out)[(size_t)gw * 32 + lane] =
        make_float2(ox > 0.f ? ox : 0.f, oy > 0.f ? oy : 0.f);
}

// ---------------- launch ----------------------------------------------------
// gemm placed 4th so the profiler's fixed sampling window captures it.
extern "C" void kernel_launch(void* const* d_in, const int* in_sizes, int n_in,
                              void* d_out, int out_size) {
    const float* x       = (const float*)d_in[0];
    const void*  ei      = d_in[1];
    const float* W       = (const float*)d_in[2];
    const float* att_src = (const float*)d_in[3];
    const float* att_dst = (const float*)d_in[4];
    const float* bias    = (const float*)d_in[5];
    float*       out     = (float*)d_out;

    init_kernel   <<<(NNODES + 255) / 256, 256>>>((const int*)ei);
    u_kernel      <<<(FEAT * 16 + 255) / 256, 256>>>(W, att_src, att_dst);
    hist_kernel   <<<(E0 + 255) / 256, 256>>>(ei);
    gemm_kernel   <<<(NNODES + BM - 1) / BM, 128>>>(x, W);
    scanA_kernel  <<<NB, 256>>>();
    scanB_kernel  <<<1, 512>>>();
    scanC_kernel  <<<(NNODES + 1 + 255) / 256, 256>>>();
    scatter_kernel<<<(E0 + 255) / 256, 256>>>(ei);
    node_kernel   <<<(NNODES * 32 + 255) / 256, 256>>>(out, bias);
}

// round 16
// speedup vs baseline: 1.1057x; 1.1057x over previous
#include <cuda_runtime.h>
#include <cuda_fp16.h>

#define NNODES 100000
#define FEAT   128
#define HEADS  8
#define HC     64          // HEADS*CH
#define E0     1600000     // edges in edge_index (self loops handled analytically)
#define NB     391         // ceil(NNODES/256) scan blocks
#define PACKW  40          // 32-bit words per node: 32 (64 fp16 h) + 8 (fp32 a_src)
#define BM     64          // gemm rows per block

// ---------------- scratch (device globals) ---------------------------------
__device__ unsigned int g_pack[NNODES * PACKW]; // 16 MB: fp16 h + fp32 a_src
__device__ float g_adst[NNODES * HEADS];        // 3.2 MB
__device__ float g_u[FEAT * 16];                // u = W @ [att_src | att_dst]
__device__ uint2 g_wfrag[16 * 8 * 32];          // 32KB: lane-ordered tf32 B frags
__device__ int   g_cnt[NNODES];                 // in-degree histogram
__device__ int   g_rowptr[NNODES + 1];          // CSR row pointers
__device__ int   g_fill[NNODES];                // scatter cursors
__device__ int   g_bsums[NB];                   // scan block sums
__device__ int   g_csr_src[E0];                 // CSR: src node per edge
__device__ int   g_is64;

// ---------------- tf32 mma helpers -----------------------------------------
__device__ __forceinline__ unsigned int f2tf32(float f) {
    unsigned int r;
    asm("cvt.rna.tf32.f32 %0, %1;" : "=r"(r) : "f"(f));
    return r;
}
__device__ __forceinline__ void mma_tf32(float c[4],
        unsigned int a0, unsigned int a1, unsigned int a2, unsigned int a3,
        unsigned int b0, unsigned int b1) {
    asm volatile(
        "mma.sync.aligned.m16n8k8.row.col.f32.tf32.tf32.f32 "
        "{%0,%1,%2,%3}, {%4,%5,%6,%7}, {%8,%9}, {%0,%1,%2,%3};"
        : "+f"(c[0]), "+f"(c[1]), "+f"(c[2]), "+f"(c[3])
        : "r"(a0), "r"(a1), "r"(a2), "r"(a3), "r"(b0), "r"(b1));
}

// ---------------- K0: zero histogram + detect dtype ------------------------
// int64 values in [0, N) have every odd 32-bit word == 0 (little endian).
__global__ void init_kernel(const int* __restrict__ ei32) {
    int t = blockIdx.x * blockDim.x + threadIdx.x;
    if (t < NNODES) g_cnt[t] = 0;
    if (t == 0) {
        int all_zero = 1;
#pragma unroll
        for (int i = 1; i < 16; i += 2) all_zero &= (ei32[i] == 0);
        g_is64 = all_zero;
    }
}

// ---------------- K0b: prep — u matrix + lane-ordered tf32 B fragments -----
// t < 2048:            u[k][j] = sum_c W[k, head*8+c] * att[c]   (exact fp32)
// t in [2048, 6144):   g_wfrag[kc][n][lane] = (B0, B1) for mma.m16n8k8
__global__ void prep_kernel(const float* __restrict__ W,
                            const float* __restrict__ att_src,
                            const float* __restrict__ att_dst) {
    int t = blockIdx.x * blockDim.x + threadIdx.x;
    if (t < FEAT * 16) {
        int k = t >> 4, j = t & 15;
        int head = j & 7;
        const float* att = (j < 8) ? (att_src + head * 8) : (att_dst + head * 8);
        float s = 0.f;
#pragma unroll
        for (int c = 0; c < 8; c++) s += W[k * HC + head * 8 + c] * att[c];
        g_u[t] = s;
    } else if (t < FEAT * 16 + 16 * 8 * 32) {
        int idx = t - FEAT * 16;
        int lane = idx & 31;
        int n = (idx >> 5) & 7;
        int kc = idx >> 8;
        int g = lane >> 2, tg = lane & 3;
        unsigned int b0 = f2tf32(W[(kc * 8 + tg)     * HC + n * 8 + g]);
        unsigned int b1 = f2tf32(W[(kc * 8 + tg + 4) * HC + n * 8 + g]);
        g_wfrag[idx] = make_uint2(b0, b1);
    }
}

// ---------------- K1: in-degree histogram (real edges only) ----------------
__global__ void hist_kernel(const void* __restrict__ ei) {
    int e = blockIdx.x * blockDim.x + threadIdx.x;
    if (e >= E0) return;
    int d = g_is64 ? ((const int*)ei)[2 * (E0 + e)]      // low word of int64
                   : ((const int*)ei)[E0 + e];
    atomicAdd(&g_cnt[d], 1);
}

// ---------------- K2a/b/c: exclusive prefix scan of g_cnt (shuffle) --------
__global__ void scanA_kernel() {
    int t = threadIdx.x, i = blockIdx.x * 256 + t;
    int lane = t & 31, w = t >> 5;
    int v = (i < NNODES) ? g_cnt[i] : 0;
    int x = v;
#pragma unroll
    for (int off = 1; off < 32; off <<= 1) {
        int y = __shfl_up_sync(0xFFFFFFFFu, x, off);
        if (lane >= off) x += y;
    }
    __shared__ int wsum[8];
    if (lane == 31) wsum[w] = x;
    __syncthreads();
    if (w == 0 && lane < 8) {
        int y = wsum[lane];
#pragma unroll
        for (int off = 1; off < 8; off <<= 1) {
            int z = __shfl_up_sync(0xFFu, y, off);
            if (lane >= off) y += z;
        }
        wsum[lane] = y;
    }
    __syncthreads();
    int incl = x + (w > 0 ? wsum[w - 1] : 0);
    if (i < NNODES) g_rowptr[i] = incl - v;       // block-local exclusive
    if (t == 255) g_bsums[blockIdx.x] = incl;
}

__global__ void scanB_kernel() {                  // 512 threads, 391 elems
    int t = threadIdx.x, lane = t & 31, w = t >> 5;
    int v = (t < NB) ? g_bsums[t] : 0;
    int x = v;
#pragma unroll
    for (int off = 1; off < 32; off <<= 1) {
        int y = __shfl_up_sync(0xFFFFFFFFu, x, off);
        if (lane >= off) x += y;
    }
    __shared__ int wsum[16];
    if (lane == 31) wsum[w] = x;
    __syncthreads();
    if (w == 0 && lane < 16) {
        int y = wsum[lane];
#pragma unroll
        for (int off = 1; off < 16; off <<= 1) {
            int z = __shfl_up_sync(0xFFFFu, y, off);
            if (lane >= off) y += z;
        }
        wsum[lane] = y;
    }
    __syncthreads();
    int incl = x + (w > 0 ? wsum[w - 1] : 0);
    if (t < NB) g_bsums[t] = incl - v;            // exclusive
}

__global__ void scanC_kernel() {
    int i = blockIdx.x * blockDim.x + threadIdx.x;
    if (i > NNODES) return;
    if (i == NNODES) { g_rowptr[NNODES] = E0; return; }
    int r = g_rowptr[i] + g_bsums[i >> 8];
    g_rowptr[i] = r;
    g_fill[i] = r;
}

// ---------------- K3: scatter edges into CSR -------------------------------
__global__ void scatter_kernel(const void* __restrict__ ei) {
    int e = blockIdx.x * blockDim.x + threadIdx.x;
    if (e >= E0) return;
    int s, d;
    const int* p = (const int*)ei;
    if (g_is64) { s = p[2 * e]; d = p[2 * (E0 + e)]; }
    else        { s = p[e];     d = p[E0 + e]; }
    int pos = atomicAdd(&g_fill[d], 1);
    g_csr_src[pos] = s;
}

// ---------------- K4: tf32 tensor-core h + exact fp32 logits ---------------
// 128 threads = 4 warps; warp w owns rows w*16..w*16+15 of a 64-row tile.
// B fragments: ONE coalesced LDG.64 per (kc,n) from L1-resident g_wfrag
// (R14's strided-W loads were the bottleneck: ~1024 L1 wavefronts/warp).
// Fragment math identical to R14 (passed, rel_err 3.0e-4).
__global__ void __launch_bounds__(128) gemm_kernel(const float* __restrict__ x,
                                                   const float* __restrict__ W) {
    __shared__ __align__(16) float xs[BM][132];    // row-major, padded
    int tid = threadIdx.x;
    int warp = tid >> 5, lane = tid & 31;
    int rowBase = blockIdx.x * BM;

    // load x tile: 64 rows x 128 floats = 2048 float4, 16 per thread.
#pragma unroll
    for (int i = 0; i < 16; i++) {
        int idx = tid + i * 128;
        int r = idx >> 5, q = idx & 31;
        int grow = rowBase + r;
        float4 v = make_float4(0.f, 0.f, 0.f, 0.f);
        if (grow < NNODES)
            v = *(const float4*)(x + (size_t)grow * FEAT + q * 4);
        *(float4*)&xs[r][q * 4] = v;
    }
    __syncthreads();

    // ---- tensor-core part: D[16x64] per warp, K=128 in 16 chunks of 8 ----
    int g = lane >> 2, tg = lane & 3;              // groupID, threadInGroup
    float c[8][4];
#pragma unroll
    for (int n = 0; n < 8; n++)
#pragma unroll
        for (int j = 0; j < 4; j++) c[n][j] = 0.f;

    for (int kc = 0; kc < 16; kc++) {
        int k0 = kc * 8;
        unsigned int A0 = f2tf32(xs[warp * 16 + g]    [k0 + tg]);
        unsigned int A1 = f2tf32(xs[warp * 16 + g + 8][k0 + tg]);
        unsigned int A2 = f2tf32(xs[warp * 16 + g]    [k0 + tg + 4]);
        unsigned int A3 = f2tf32(xs[warp * 16 + g + 8][k0 + tg + 4]);
        const uint2* wf = g_wfrag + (size_t)kc * 256 + lane;
#pragma unroll
        for (int n = 0; n < 8; n++) {
            uint2 b = __ldg(wf + n * 32);
            mma_tf32(c[n], A0, A1, A2, A3, b.x, b.y);
        }
    }

    // store h as fp16: c0/c1 are cols (2*tg, 2*tg+1) of row g; c2/c3 row g+8.
#pragma unroll
    for (int n = 0; n < 8; n++) {
        int rlo = rowBase + warp * 16 + g;
        int rhi = rlo + 8;
        __half2 lo = __floats2half2_rn(c[n][0], c[n][1]);
        __half2 hi = __floats2half2_rn(c[n][2], c[n][3]);
        if (rlo < NNODES) g_pack[(size_t)rlo * PACKW + n * 4 + tg] = *(unsigned int*)&lo;
        if (rhi < NNODES) g_pack[(size_t)rhi * PACKW + n * 4 + tg] = *(unsigned int*)&hi;
    }

    // ---- exact fp32 logits: lane = 2*r + half; 8 u-cols per lane ----------
    int r = lane >> 1, half = lane & 1;
    int srow = warp * 16 + r;
    int grow = rowBase + srow;
    float acc[8];
#pragma unroll
    for (int j = 0; j < 8; j++) acc[j] = 0.f;
    for (int k4 = 0; k4 < FEAT; k4 += 4) {
        float4 xv = *(const float4*)&xs[srow][k4];
        float xk[4] = {xv.x, xv.y, xv.z, xv.w};
#pragma unroll
        for (int kk = 0; kk < 4; kk++) {
            int k = k4 + kk;
            float4 ua = __ldg((const float4*)(g_u + k * 16 + half * 8));
            float4 ub = __ldg((const float4*)(g_u + k * 16 + half * 8 + 4));
            acc[0] += xk[kk] * ua.x; acc[1] += xk[kk] * ua.y;
            acc[2] += xk[kk] * ua.z; acc[3] += xk[kk] * ua.w;
            acc[4] += xk[kk] * ub.x; acc[5] += xk[kk] * ub.y;
            acc[6] += xk[kk] * ub.z; acc[7] += xk[kk] * ub.w;
        }
    }
    if (grow < NNODES) {
        if (half == 0) {        // a_src → packed row words 32..39
            float* dst = (float*)(g_pack + (size_t)grow * PACKW + 32);
            *(float4*)dst       = make_float4(acc[0], acc[1], acc[2], acc[3]);
            *(float4*)(dst + 4) = make_float4(acc[4], acc[5], acc[6], acc[7]);
        } else {                // a_dst
            float* dst = g_adst + (size_t)grow * 8;
            *(float4*)dst       = make_float4(acc[0], acc[1], acc[2], acc[3]);
            *(float4*)(dst + 4) = make_float4(acc[4], acc[5], acc[6], acc[7]);
        }
    }
}

// ---------------- K5: fused single-pass softmax + aggregate + bias + relu --
// One warp per destination node. Lane l owns channels {2l,2l+1}, head l>>2.
// Per edge: ONE 160B row (4 sectors fp16 h + 1 sector fp32 a_src).
__global__ void node_kernel(float* __restrict__ out, const float* __restrict__ bias) {
    int gw = (blockIdx.x * blockDim.x + threadIdx.x) >> 5;
    if (gw >= NNODES) return;
    int lane = threadIdx.x & 31;
    int beg = g_rowptr[gw], end = g_rowptr[gw + 1];
    int hd = lane >> 2;
    float adst = g_adst[gw * 8 + hd];

    // self loop
    const unsigned int* prow = g_pack + (size_t)gw * PACKW;
    float vs = __uint_as_float(prow[32 + hd]) + adst;
    vs = vs > 0.f ? vs : 0.2f * vs;
    float exs = __expf(vs);
    float2 hs = __half22float2(*(const __half2*)(prow + lane));
    float denom = exs;
    float ax = exs * hs.x, ay = exs * hs.y;

    int j = beg;
    for (; j + 4 <= end; j += 4) {
        int s0 = __ldg(&g_csr_src[j]);
        int s1 = __ldg(&g_csr_src[j + 1]);
        int s2 = __ldg(&g_csr_src[j + 2]);
        int s3 = __ldg(&g_csr_src[j + 3]);
        const unsigned int* p0 = g_pack + (size_t)s0 * PACKW;
        const unsigned int* p1 = g_pack + (size_t)s1 * PACKW;
        const unsigned int* p2 = g_pack + (size_t)s2 * PACKW;
        const unsigned int* p3 = g_pack + (size_t)s3 * PACKW;
        float e0 = __uint_as_float(p0[32 + hd]);
        float e1 = __uint_as_float(p1[32 + hd]);
        float e2 = __uint_as_float(p2[32 + hd]);
        float e3 = __uint_as_float(p3[32 + hd]);
        __half2 q0 = *(const __half2*)(p0 + lane);
        __half2 q1 = *(const __half2*)(p1 + lane);
        __half2 q2 = *(const __half2*)(p2 + lane);
        __half2 q3 = *(const __half2*)(p3 + lane);
        float v0 = e0 + adst; v0 = v0 > 0.f ? v0 : 0.2f * v0;
        float v1 = e1 + adst; v1 = v1 > 0.f ? v1 : 0.2f * v1;
        float v2 = e2 + adst; v2 = v2 > 0.f ? v2 : 0.2f * v2;
        float v3 = e3 + adst; v3 = v3 > 0.f ? v3 : 0.2f * v3;
        float x0 = __expf(v0), x1 = __expf(v1), x2 = __expf(v2), x3 = __expf(v3);
        float2 h0 = __half22float2(q0);
        float2 h1 = __half22float2(q1);
        float2 h2v = __half22float2(q2);
        float2 h3 = __half22float2(q3);
        denom += (x0 + x1) + (x2 + x3);
        ax += x0 * h0.x + x1 * h1.x + x2 * h2v.x + x3 * h3.x;
        ay += x0 * h0.y + x1 * h1.y + x2 * h2v.y + x3 * h3.y;
    }
    for (; j < end; j++) {
        int s = __ldg(&g_csr_src[j]);
        const unsigned int* p = g_pack + (size_t)s * PACKW;
        float v = __uint_as_float(p[32 + hd]) + adst;
        v = v > 0.f ? v : 0.2f * v;
        float ex = __expf(v);
        float2 hv = __half22float2(*(const __half2*)(p + lane));
        denom += ex;
        ax += ex * hv.x;
        ay += ex * hv.y;
    }

    float inv = __fdividef(1.f, denom + 1e-16f);
    float2 b = ((const float2*)bias)[lane];
    float ox = ax * inv + b.x, oy = ay * inv + b.y;
    ((float2*)out)[(size_t)gw * 32 + lane] =
        make_float2(ox > 0.f ? ox : 0.f, oy > 0.f ? oy : 0.f);
}

// ---------------- launch ----------------------------------------------------
// gemm placed 4th so the profiler's fixed sampling window captures it.
extern "C" void kernel_launch(void* const* d_in, const int* in_sizes, int n_in,
                              void* d_out, int out_size) {
    const float* x       = (const float*)d_in[0];
    const void*  ei      = d_in[1];
    const float* W       = (const float*)d_in[2];
    const float* att_src = (const float*)d_in[3];
    const float* att_dst = (const float*)d_in[4];
    const float* bias    = (const float*)d_in[5];
    float*       out     = (float*)d_out;

    init_kernel   <<<(NNODES + 255) / 256, 256>>>((const int*)ei);
    prep_kernel   <<<(FEAT * 16 + 16 * 8 * 32 + 255) / 256, 256>>>(W, att_src, att_dst);
    hist_kernel   <<<(E0 + 255) / 256, 256>>>(ei);
    gemm_kernel   <<<(NNODES + BM - 1) / BM, 128>>>(x, W);
    scanA_kernel  <<<NB, 256>>>();
    scanB_kernel  <<<1, 512>>>();
    scanC_kernel  <<<(NNODES + 1 + 255) / 256, 256>>>();
    scatter_kernel<<<(E0 + 255) / 256, 256>>>(ei);
    node_kernel   <<<(NNODES * 32 + 255) / 256, 256>>>(out, bias);
}